// round 16
// baseline (speedup 1.0000x reference)
#include <cuda_runtime.h>
#include <cuda_fp16.h>
#include <math.h>
#include <stdint.h>

#define BB 16
#define LL 1024
#define DD 1024
#define HH 8
#define KHD 128
#define OUTN 64

typedef __half  h16;
typedef __half2 h162;

// ---------------- scratch ----------------
__device__ h16 g_x0h[BB*LL*DD];
__device__ h16 g_x1h[BB*LL*DD];
__device__ h16 g_x2h[BB*LL*DD];
__device__ h16 g_wk[DD*DD], g_wq[DD*DD], g_wv[DD*DD], g_wu[DD*DD];
__device__ h16 g_qq[BB*LL*DD], g_kk[BB*LL*DD], g_vv[BB*LL*DD];
__device__ h16 g_att[BB*LL*DD];
__device__ float    g_psum[BB*DD];
__device__ unsigned g_pmax[BB*DD];

// ---------------- helpers ----------------
__device__ __forceinline__ uint32_t pkh(h16 x, h16 y) {
    h162 t; t.x = x; t.y = y; return *(uint32_t*)&t;
}
// .ca: keep staged lines in L1 — operand tiles are shared across co-resident CTAs
__device__ __forceinline__ void cpa16(void* s, const void* g) {
    uint32_t sa = (uint32_t)__cvta_generic_to_shared(s);
    asm volatile("cp.async.ca.shared.global [%0], [%1], 16;" :: "r"(sa), "l"(g));
}
__device__ __forceinline__ void cp_commit() {
    asm volatile("cp.async.commit_group;" ::: "memory");
}
__device__ __forceinline__ void cp_wait1() {
    asm volatile("cp.async.wait_group 1;" ::: "memory");
}
__device__ __forceinline__ void cp_wait2() {
    asm volatile("cp.async.wait_group 2;" ::: "memory");
}
__device__ __forceinline__ void ldsm_x4(uint32_t* r, const void* p) {
    uint32_t a = (uint32_t)__cvta_generic_to_shared(p);
    asm volatile("ldmatrix.sync.aligned.m8n8.x4.shared.b16 {%0,%1,%2,%3}, [%4];"
        : "=r"(r[0]), "=r"(r[1]), "=r"(r[2]), "=r"(r[3]) : "r"(a));
}
__device__ __forceinline__ void ldsm_x4t(uint32_t* r, const void* p) {
    uint32_t a = (uint32_t)__cvta_generic_to_shared(p);
    asm volatile("ldmatrix.sync.aligned.m8n8.x4.trans.shared.b16 {%0,%1,%2,%3}, [%4];"
        : "=r"(r[0]), "=r"(r[1]), "=r"(r[2]), "=r"(r[3]) : "r"(a));
}
__device__ __forceinline__ void mma_f16(float* c, const uint32_t* a, const uint32_t* b) {
    asm volatile(
        "mma.sync.aligned.m16n8k16.row.col.f32.f16.f16.f32 "
        "{%0,%1,%2,%3},{%4,%5,%6,%7},{%8,%9},{%0,%1,%2,%3};"
        : "+f"(c[0]), "+f"(c[1]), "+f"(c[2]), "+f"(c[3])
        : "r"(a[0]), "r"(a[1]), "r"(a[2]), "r"(a[3]), "r"(b[0]), "r"(b[1]));
}
__device__ __forceinline__ unsigned fkey(float v) {
    unsigned u = __float_as_uint(v);
    return (u & 0x80000000u) ? ~u : (u | 0x80000000u);
}
__device__ __forceinline__ float fdec(unsigned k) {
    unsigned u = (k & 0x80000000u) ? (k ^ 0x80000000u) : ~k;
    return __uint_as_float(u);
}

// ---- shared GEMM mainloop core: BM=BN=128, BK=32, 4-buffer ring ----
#define GEMM_CORE(Ax, Bx)                                                   \
    constexpr int RS  = 40;                                                 \
    constexpr int ARR = 128 * RS;                                           \
    constexpr int STG = 2 * ARR;                                            \
    const int u = threadIdx.x, wid = u >> 5, lane = u & 31;                 \
    const int wm = (wid >> 2) * 64, wn = (wid & 3) * 32;                    \
    float acc[4][4][4];                                                     \
    _Pragma("unroll")                                                       \
    for (int i = 0; i < 4; ++i)                                             \
        _Pragma("unroll")                                                   \
        for (int j = 0; j < 4; ++j)                                         \
            _Pragma("unroll")                                               \
            for (int p = 0; p < 4; ++p) acc[i][j][p] = 0.f;                 \
    const int srow = u >> 1, scol = (u & 1) * 16;                           \
    auto stage = [&](int buf, int k0) {                                     \
        h16* s0 = (h16*)smem + (long)buf * STG + srow * RS + scol;          \
        const long ga = (long)(bm + srow) * DD + k0 + scol;                 \
        const long gb = (long)(bn + srow) * DD + k0 + scol;                 \
        cpa16(s0,           Ax + ga);                                       \
        cpa16(s0 + 8,       Ax + ga + 8);                                   \
        cpa16(s0 + ARR,     Bx + gb);                                       \
        cpa16(s0 + ARR + 8, Bx + gb + 8);                                   \
    };                                                                      \
    constexpr int nst = DD / 32;                                            \
    _Pragma("unroll")                                                       \
    for (int t = 0; t < 3; ++t) { stage(t, t * 32); cp_commit(); }          \
    const int arow = lane & 15, asel = (lane >> 4) * 8;                     \
    const int brow = ((lane >> 4) & 1) * 8 + (lane & 7);                    \
    const int bcol = ((lane >> 3) & 1) * 8;                                 \
    for (int s = 0; s < nst; ++s) {                                         \
        cp_wait2();                                                         \
        __syncthreads();                                                    \
        if (s + 3 < nst) stage((s + 3) & 3, (s + 3) * 32);                  \
        cp_commit();                                                        \
        const h16* base = (const h16*)smem + (long)(s & 3) * STG;           \
        const h16* sA = base;                                               \
        const h16* sB = base + ARR;                                         \
        _Pragma("unroll")                                                   \
        for (int kk = 0; kk < 32; kk += 16) {                               \
            uint32_t ah[4][4];                                              \
            _Pragma("unroll")                                               \
            for (int mt = 0; mt < 4; ++mt)                                  \
                ldsm_x4(ah[mt], sA + (wm + mt * 16 + arow) * RS + kk + asel); \
            _Pragma("unroll")                                               \
            for (int np = 0; np < 2; ++np) {                                \
                uint32_t bh4[4];                                            \
                ldsm_x4(bh4, sB + (wn + np * 16 + brow) * RS + kk + bcol);  \
                _Pragma("unroll")                                           \
                for (int half = 0; half < 2; ++half) {                      \
                    const int nt = np * 2 + half;                           \
                    _Pragma("unroll")                                       \
                    for (int mt = 0; mt < 4; ++mt)                          \
                        mma_f16(acc[mt][nt], ah[mt], bh4 + half * 2);       \
                }                                                           \
            }                                                               \
        }                                                                   \
    }

// =================================================================
// Projections: fp16 1-MMA TN GEMM, z-batched over {q,k,v}.
// =================================================================
__global__ void __launch_bounds__(256, 2)
gemm_proj(const h16* __restrict__ A0, const h16* __restrict__ B0, h16* __restrict__ C0,
          const h16* __restrict__ A1, const h16* __restrict__ B1, h16* __restrict__ C1,
          const h16* __restrict__ A2, const h16* __restrict__ B2, h16* __restrict__ C2)
{
    extern __shared__ __align__(16) char smem[];
    const h16* Ax = (blockIdx.z == 0) ? A0 : (blockIdx.z == 1) ? A1 : A2;
    const h16* Bx = (blockIdx.z == 0) ? B0 : (blockIdx.z == 1) ? B1 : B2;
    h16*       Cx = (blockIdx.z == 0) ? C0 : (blockIdx.z == 1) ? C1 : C2;
    const int bm = blockIdx.y * 128, bn = blockIdx.x * 128;

    GEMM_CORE(Ax, Bx)

    const int tr = lane >> 2, tc = lane & 3;
    #pragma unroll
    for (int mt = 0; mt < 4; ++mt) {
        const int row = bm + wm + mt * 16 + tr;
        #pragma unroll
        for (int nt = 0; nt < 4; ++nt) {
            const int col = bn + wn + nt * 8 + tc * 2;
            const float* c = acc[mt][nt];
            *(uint32_t*)&Cx[(long)row * DD + col] =
                pkh(__float2half_rn(c[0]), __float2half_rn(c[1]));
            *(uint32_t*)&Cx[(long)(row + 8) * DD + col] =
                pkh(__float2half_rn(c[2]), __float2half_rn(c[3]));
        }
    }
}

// =================================================================
// Unify GEMM + fused mean/max pooling epilogue.
// =================================================================
__global__ void __launch_bounds__(256, 2)
gemm_uni(const h16* __restrict__ Ain, const h16* __restrict__ Bin,
         const float* __restrict__ bias,
         float* __restrict__ psum, unsigned* __restrict__ pmax)
{
    extern __shared__ __align__(16) char smem[];
    const int bm = blockIdx.y * 128, bn = blockIdx.x * 128;

    GEMM_CORE(Ain, Bin)

    const int tr = lane >> 2, tc = lane & 3;
    const int b = bm >> 10;
    float sum[4][2], mx[4][2];
    #pragma unroll
    for (int nt = 0; nt < 4; ++nt) {
        #pragma unroll
        for (int j = 0; j < 2; ++j) {
            const int col = bn + wn + nt * 8 + tc * 2 + j;
            const float bv = __ldg(bias + col);
            float s_ = 0.f, m_ = -1e30f;
            #pragma unroll
            for (int mt = 0; mt < 4; ++mt) {
                const float v0 = acc[mt][nt][j] + bv;
                const float v1 = acc[mt][nt][j + 2] + bv;
                s_ += v0 + v1;
                m_ = fmaxf(m_, fmaxf(v0, v1));
            }
            sum[nt][j] = s_; mx[nt][j] = m_;
        }
    }
    #pragma unroll
    for (int o = 4; o <= 16; o <<= 1) {
        #pragma unroll
        for (int nt = 0; nt < 4; ++nt)
            #pragma unroll
            for (int j = 0; j < 2; ++j) {
                sum[nt][j] += __shfl_xor_sync(~0u, sum[nt][j], o);
                mx[nt][j] = fmaxf(mx[nt][j], __shfl_xor_sync(~0u, mx[nt][j], o));
            }
    }
    if (tr == 0) {
        #pragma unroll
        for (int nt = 0; nt < 4; ++nt)
            #pragma unroll
            for (int j = 0; j < 2; ++j) {
                const int col = bn + wn + nt * 8 + tc * 2 + j;
                atomicAdd(&psum[b * DD + col], sum[nt][j]);
                atomicMax(&pmax[b * DD + col], fkey(mx[nt][j]));
            }
    }
}

// =================================================================
// Fused flash attention — full fp16 (unchanged from R15).
// =================================================================
__global__ void __launch_bounds__(256, 2)
flash_k(const h16* __restrict__ Q, const h16* __restrict__ K,
        const h16* __restrict__ V, h16* __restrict__ O_)
{
    extern __shared__ __align__(16) char sm[];
    constexpr int QS = 128 * 136;
    constexpr int TS = 64 * 136;
    h16* sQ = (h16*)sm;
    h16* sT = sQ + QS;
    constexpr float SC2 = 0.08838834764831845f;   // 1/sqrt(128)

    const int bh = blockIdx.y, b = bh >> 3, h = bh & 7;
    const int q0 = blockIdx.x * 128;
    const int u = threadIdx.x, wid = u >> 5, lane = u & 31;
    const int tr = lane >> 2, tc = lane & 3;

    const long qg = ((long)b * LL + q0) * DD + h * KHD;
    const long kg = (long)b * LL * DD + h * KHD;

    for (int c = u; c < 2048; c += 256) {
        const int r = c >> 4, s = (c & 15) * 8;
        cpa16(sQ + r * 136 + s, Q + qg + (long)r * DD + s);
    }
    auto stage = [&](int buf, int kv0) {
        h16* pK = sT + buf * 2 * TS;
        h16* pV = pK + TS;
        for (int c = u; c < 1024; c += 256) {
            const int r = c >> 4, s = (c & 15) * 8;
            const long g = kg + (long)(kv0 + r) * DD + s;
            cpa16(pK + r * 136 + s, K + g);
            cpa16(pV + r * 136 + s, V + g);
        }
    };
    stage(0, 0);
    cp_commit();

    float O[16][4];
    #pragma unroll
    for (int i = 0; i < 16; ++i)
        #pragma unroll
        for (int j = 0; j < 4; ++j) O[i][j] = 0.f;
    float m0 = -1e30f, m1 = -1e30f, l0 = 0.f, l1 = 0.f;

    const int brow = ((lane >> 4) & 1) * 8 + (lane & 7);
    const int bcol = ((lane >> 3) & 1) * 8;
    const int vrow = ((lane >> 3) & 1) * 8 + (lane & 7);
    const int vsel = (lane >> 4);

    for (int t = 0; t < 16; ++t) {
        if (t + 1 < 16) stage((t + 1) & 1, (t + 1) * 64);
        cp_commit();
        cp_wait1();
        __syncthreads();

        const h16* cK = sT + (t & 1) * 2 * TS;
        const h16* cV = cK + TS;

        float S[8][4];
        #pragma unroll
        for (int i = 0; i < 8; ++i)
            #pragma unroll
            for (int j = 0; j < 4; ++j) S[i][j] = 0.f;

        #pragma unroll
        for (int kk = 0; kk < 128; kk += 16) {
            uint32_t ah[4];
            const int aoff = (wid * 16 + (lane & 15)) * 136 + kk + (lane >> 4) * 8;
            ldsm_x4(ah, sQ + aoff);
            #pragma unroll
            for (int np = 0; np < 4; ++np) {
                uint32_t bh4[4];
                const int boff = (np * 16 + brow) * 136 + kk + bcol;
                ldsm_x4(bh4, cK + boff);
                mma_f16(S[np * 2],     ah, bh4);
                mma_f16(S[np * 2 + 1], ah, bh4 + 2);
            }
        }

        float rm0 = -1e30f, rm1 = -1e30f;
        #pragma unroll
        for (int nt = 0; nt < 8; ++nt) {
            rm0 = fmaxf(rm0, fmaxf(S[nt][0], S[nt][1]));
            rm1 = fmaxf(rm1, fmaxf(S[nt][2], S[nt][3]));
        }
        rm0 = fmaxf(rm0, __shfl_xor_sync(~0u, rm0, 1));
        rm0 = fmaxf(rm0, __shfl_xor_sync(~0u, rm0, 2));
        rm1 = fmaxf(rm1, __shfl_xor_sync(~0u, rm1, 1));
        rm1 = fmaxf(rm1, __shfl_xor_sync(~0u, rm1, 2));
        const float M0 = fmaxf(m0, rm0), M1 = fmaxf(m1, rm1);
        const float f0 = __expf((m0 - M0) * SC2), f1 = __expf((m1 - M1) * SC2);
        m0 = M0; m1 = M1;
        l0 *= f0; l1 *= f1;
        #pragma unroll
        for (int dt = 0; dt < 16; ++dt) {
            O[dt][0] *= f0; O[dt][1] *= f0;
            O[dt][2] *= f1; O[dt][3] *= f1;
        }

        #pragma unroll
        for (int kc = 0; kc < 4; ++kc) {
            uint32_t pa[4];
            #pragma unroll
            for (int half = 0; half < 2; ++half) {
                const int nt = kc * 2 + half;
                const float p0 = __expf((S[nt][0] - M0) * SC2);
                const float p1 = __expf((S[nt][1] - M0) * SC2);
                const float p2 = __expf((S[nt][2] - M1) * SC2);
                const float p3 = __expf((S[nt][3] - M1) * SC2);
                l0 += p0 + p1; l1 += p2 + p3;
                pa[half ? 2 : 0] = pkh(__float2half_rn(p0), __float2half_rn(p1));
                pa[half ? 3 : 1] = pkh(__float2half_rn(p2), __float2half_rn(p3));
            }
            #pragma unroll
            for (int dt = 0; dt < 16; dt += 2) {
                uint32_t bv[4];
                const int voff = (kc * 16 + vrow) * 136 + (dt + vsel) * 8;
                ldsm_x4t(bv, cV + voff);
                mma_f16(O[dt],     pa, bv);
                mma_f16(O[dt + 1], pa, bv + 2);
            }
        }
        __syncthreads();
    }

    l0 += __shfl_xor_sync(~0u, l0, 1); l0 += __shfl_xor_sync(~0u, l0, 2);
    l1 += __shfl_xor_sync(~0u, l1, 1); l1 += __shfl_xor_sync(~0u, l1, 2);
    const float i0 = 1.f / l0, i1 = 1.f / l1;
    const long og = ((long)b * LL + q0 + wid * 16) * DD + h * KHD;
    #pragma unroll
    for (int dt = 0; dt < 16; ++dt) {
        const int col = dt * 8 + tc * 2;
        *(uint32_t*)&O_[og + (long)tr * DD + col] =
            pkh(__float2half_rn(O[dt][0] * i0), __float2half_rn(O[dt][1] * i0));
        *(uint32_t*)&O_[og + (long)(tr + 8) * DD + col] =
            pkh(__float2half_rn(O[dt][2] * i1), __float2half_rn(O[dt][3] * i1));
    }
}

// ---------------- converts ----------------
__device__ __forceinline__ void conv4_h(const float* in, h16* hi, int i)
{
    const float4 v = ((const float4*)in)[i];
    ((uint32_t*)hi)[i * 2]     = pkh(__float2half_rn(v.x), __float2half_rn(v.y));
    ((uint32_t*)hi)[i * 2 + 1] = pkh(__float2half_rn(v.z), __float2half_rn(v.w));
}

__global__ void conv_x(const float* __restrict__ x1, h16* __restrict__ x1h,
                       const float* __restrict__ x2, h16* __restrict__ x2h,
                       const float* __restrict__ x0, h16* __restrict__ x0h)
{
    const int i = blockIdx.x * 256 + threadIdx.x;
    switch (blockIdx.y) {
        case 0: conv4_h(x1, x1h, i); break;
        case 1: conv4_h(x2, x2h, i); break;
        default: conv4_h(x0, x0h, i); break;
    }
}
// weights + pool-init fused (one launch)
__global__ void conv_w(const float* __restrict__ Wk, h16* __restrict__ wk,
                       const float* __restrict__ Wq, h16* __restrict__ wq,
                       const float* __restrict__ Wv, h16* __restrict__ wv,
                       const float* __restrict__ Wu, h16* __restrict__ wu,
                       float* __restrict__ psum, unsigned* __restrict__ pmax)
{
    const int i = blockIdx.x * 256 + threadIdx.x;
    switch (blockIdx.y) {
        case 0: conv4_h(Wk, wk, i); break;
        case 1: conv4_h(Wq, wq, i); break;
        case 2: conv4_h(Wv, wv, i); break;
        case 3: conv4_h(Wu, wu, i); break;
        default:
            if (i < BB * DD / 4) {
                ((float4*)psum)[i] = make_float4(0.f, 0.f, 0.f, 0.f);
                ((uint4*)pmax)[i]  = make_uint4(0u, 0u, 0u, 0u);
            }
            break;
    }
}

// ---------------- logits ----------------
__global__ void logits_kernel(const float* __restrict__ psum,
                              const unsigned* __restrict__ pmax,
                              const float* __restrict__ Wm,
                              const float* __restrict__ bm,
                              float* __restrict__ out)
{
    const int b = blockIdx.x;
    __shared__ float ps[DD];
    __shared__ float red[4][OUTN];
    for (int i = threadIdx.x; i < DD; i += 256)
        ps[i] = psum[b * DD + i] * (1.f / LL) + fdec(pmax[b * DD + i]);
    __syncthreads();
    const int o = threadIdx.x & 63, part = threadIdx.x >> 6;
    float s = 0.f;
    const float* w = Wm + (long)o * DD + part * 256;
    const float* p = ps + part * 256;
    #pragma unroll 8
    for (int kk = 0; kk < 256; ++kk) s += p[kk] * w[kk];
    red[part][o] = s;
    __syncthreads();
    if (part == 0)
        out[b * OUTN + o] = red[0][o] + red[1][o] + red[2][o] + red[3][o] + bm[o];
}

// =================================================================
extern "C" void kernel_launch(void* const* d_in, const int* in_sizes, int n_in,
                              void* d_out, int out_size)
{
    const float* x0   = (const float*)d_in[0];
    const float* x1   = (const float*)d_in[1];
    const float* x2   = (const float*)d_in[2];
    const float* Wk   = (const float*)d_in[5];
    const float* Wq   = (const float*)d_in[6];
    const float* Wv   = (const float*)d_in[7];
    const float* Wu   = (const float*)d_in[8];
    const float* bu   = (const float*)d_in[9];
    const float* Wmlp = (const float*)d_in[10];
    const float* bmlp = (const float*)d_in[11];
    float* out = (float*)d_out;

    h16 *x0h,*x1h,*x2h,*wk,*wq,*wv,*wu,*qq,*kk,*vv,*att;
    float *psum; unsigned *pmax;
    cudaGetSymbolAddress((void**)&x0h, g_x0h);
    cudaGetSymbolAddress((void**)&x1h, g_x1h);
    cudaGetSymbolAddress((void**)&x2h, g_x2h);
    cudaGetSymbolAddress((void**)&wk,  g_wk);
    cudaGetSymbolAddress((void**)&wq,  g_wq);
    cudaGetSymbolAddress((void**)&wv,  g_wv);
    cudaGetSymbolAddress((void**)&wu,  g_wu);
    cudaGetSymbolAddress((void**)&qq,  g_qq);
    cudaGetSymbolAddress((void**)&kk,  g_kk);
    cudaGetSymbolAddress((void**)&vv,  g_vv);
    cudaGetSymbolAddress((void**)&att, g_att);
    cudaGetSymbolAddress((void**)&psum, g_psum);
    cudaGetSymbolAddress((void**)&pmax, g_pmax);

    const int M = BB * LL;

    constexpr int SM_PRJ = 4 * 2 * 128 * 40 * 2;               // 81920
    constexpr int SM_FL  = (128 * 136 + 2 * 2 * 64 * 136) * 2; // 104448
    cudaFuncSetAttribute(gemm_proj, cudaFuncAttributeMaxDynamicSharedMemorySize, SM_PRJ);
    cudaFuncSetAttribute(gemm_uni,  cudaFuncAttributeMaxDynamicSharedMemorySize, SM_PRJ);
    cudaFuncSetAttribute(flash_k,   cudaFuncAttributeMaxDynamicSharedMemorySize, SM_FL);

    // --- converts (+ fused pool init) ---
    {
        dim3 gx(BB * LL * DD / 4 / 256, 3);
        conv_x<<<gx, 256>>>(x1, x1h, x2, x2h, x0, x0h);
        dim3 gw(DD * DD / 4 / 256, 5);
        conv_w<<<gw, 256>>>(Wk, wk, Wq, wq, Wv, wv, Wu, wu, psum, pmax);
    }

    dim3 blk(256);

    // --- q, k, v projections (one z=3 launch) ---
    {
        dim3 g3(DD / 128, M / 128, 3);
        gemm_proj<<<g3, blk, SM_PRJ>>>(x2h, wk, qq,
                                       x1h, wq, kk,
                                       x0h, wv, vv);
    }

    // --- fused attention ---
    {
        dim3 grid(LL / 128, BB * HH);
        flash_k<<<grid, blk, SM_FL>>>(qq, kk, vv, att);
    }

    // --- unify + fused pooling ---
    {
        dim3 g1(DD / 128, M / 128);
        gemm_uni<<<g1, blk, SM_PRJ>>>(att, wu, bu, psum, pmax);
    }

    // --- logits ---
    logits_kernel<<<BB, 256>>>(psum, pmax, Wmlp, bmlp, out);
}

// round 17
// speedup vs baseline: 1.0993x; 1.0993x over previous
#include <cuda_runtime.h>
#include <cuda_fp16.h>
#include <math.h>
#include <stdint.h>

#define BB 16
#define LL 1024
#define DD 1024
#define HH 8
#define KHD 128
#define OUTN 64

typedef __half  h16;
typedef __half2 h162;

// ---------------- scratch ----------------
__device__ h16 g_x0h[BB*LL*DD];
__device__ h16 g_x1h[BB*LL*DD];
__device__ h16 g_x2h[BB*LL*DD];
__device__ h16 g_wk[DD*DD], g_wq[DD*DD], g_wv[DD*DD], g_wu[DD*DD];
__device__ h16 g_qq[BB*LL*DD], g_kk[BB*LL*DD], g_vv[BB*LL*DD];
__device__ h16 g_att[BB*LL*DD];
__device__ float    g_psum[BB*DD];
__device__ unsigned g_pmax[BB*DD];

// ---------------- helpers ----------------
__device__ __forceinline__ uint32_t pkh(h16 x, h16 y) {
    h162 t; t.x = x; t.y = y; return *(uint32_t*)&t;
}
// .cg: bypass L1 — validated fastest (R15); .ca regressed (R16).
__device__ __forceinline__ void cpa16(void* s, const void* g) {
    uint32_t sa = (uint32_t)__cvta_generic_to_shared(s);
    asm volatile("cp.async.cg.shared.global [%0], [%1], 16;" :: "r"(sa), "l"(g));
}
__device__ __forceinline__ void cp_commit() {
    asm volatile("cp.async.commit_group;" ::: "memory");
}
__device__ __forceinline__ void cp_wait1() {
    asm volatile("cp.async.wait_group 1;" ::: "memory");
}
__device__ __forceinline__ void cp_wait2() {
    asm volatile("cp.async.wait_group 2;" ::: "memory");
}
__device__ __forceinline__ void ldsm_x4(uint32_t* r, const void* p) {
    uint32_t a = (uint32_t)__cvta_generic_to_shared(p);
    asm volatile("ldmatrix.sync.aligned.m8n8.x4.shared.b16 {%0,%1,%2,%3}, [%4];"
        : "=r"(r[0]), "=r"(r[1]), "=r"(r[2]), "=r"(r[3]) : "r"(a));
}
__device__ __forceinline__ void ldsm_x4t(uint32_t* r, const void* p) {
    uint32_t a = (uint32_t)__cvta_generic_to_shared(p);
    asm volatile("ldmatrix.sync.aligned.m8n8.x4.trans.shared.b16 {%0,%1,%2,%3}, [%4];"
        : "=r"(r[0]), "=r"(r[1]), "=r"(r[2]), "=r"(r[3]) : "r"(a));
}
__device__ __forceinline__ void mma_f16(float* c, const uint32_t* a, const uint32_t* b) {
    asm volatile(
        "mma.sync.aligned.m16n8k16.row.col.f32.f16.f16.f32 "
        "{%0,%1,%2,%3},{%4,%5,%6,%7},{%8,%9},{%0,%1,%2,%3};"
        : "+f"(c[0]), "+f"(c[1]), "+f"(c[2]), "+f"(c[3])
        : "r"(a[0]), "r"(a[1]), "r"(a[2]), "r"(a[3]), "r"(b[0]), "r"(b[1]));
}
__device__ __forceinline__ unsigned fkey(float v) {
    unsigned u = __float_as_uint(v);
    return (u & 0x80000000u) ? ~u : (u | 0x80000000u);
}
__device__ __forceinline__ float fdec(unsigned k) {
    unsigned u = (k & 0x80000000u) ? (k ^ 0x80000000u) : ~k;
    return __uint_as_float(u);
}

// ---- shared GEMM mainloop core: BM=BN=128, BK=32, 4-buffer ring ----
#define GEMM_CORE(Ax, Bx)                                                   \
    constexpr int RS  = 40;                                                 \
    constexpr int ARR = 128 * RS;                                           \
    constexpr int STG = 2 * ARR;                                            \
    const int u = threadIdx.x, wid = u >> 5, lane = u & 31;                 \
    const int wm = (wid >> 2) * 64, wn = (wid & 3) * 32;                    \
    float acc[4][4][4];                                                     \
    _Pragma("unroll")                                                       \
    for (int i = 0; i < 4; ++i)                                             \
        _Pragma("unroll")                                                   \
        for (int j = 0; j < 4; ++j)                                         \
            _Pragma("unroll")                                               \
            for (int p = 0; p < 4; ++p) acc[i][j][p] = 0.f;                 \
    const int srow = u >> 1, scol = (u & 1) * 16;                           \
    auto stage = [&](int buf, int k0) {                                     \
        h16* s0 = (h16*)smem + (long)buf * STG + srow * RS + scol;          \
        const long ga = (long)(bm + srow) * DD + k0 + scol;                 \
        const long gb = (long)(bn + srow) * DD + k0 + scol;                 \
        cpa16(s0,           Ax + ga);                                       \
        cpa16(s0 + 8,       Ax + ga + 8);                                   \
        cpa16(s0 + ARR,     Bx + gb);                                       \
        cpa16(s0 + ARR + 8, Bx + gb + 8);                                   \
    };                                                                      \
    constexpr int nst = DD / 32;                                            \
    _Pragma("unroll")                                                       \
    for (int t = 0; t < 3; ++t) { stage(t, t * 32); cp_commit(); }          \
    const int arow = lane & 15, asel = (lane >> 4) * 8;                     \
    const int brow = ((lane >> 4) & 1) * 8 + (lane & 7);                    \
    const int bcol = ((lane >> 3) & 1) * 8;                                 \
    for (int s = 0; s < nst; ++s) {                                         \
        cp_wait2();                                                         \
        __syncthreads();                                                    \
        if (s + 3 < nst) stage((s + 3) & 3, (s + 3) * 32);                  \
        cp_commit();                                                        \
        const h16* base = (const h16*)smem + (long)(s & 3) * STG;           \
        const h16* sA = base;                                               \
        const h16* sB = base + ARR;                                         \
        _Pragma("unroll")                                                   \
        for (int kk = 0; kk < 32; kk += 16) {                               \
            uint32_t ah[4][4];                                              \
            _Pragma("unroll")                                               \
            for (int mt = 0; mt < 4; ++mt)                                  \
                ldsm_x4(ah[mt], sA + (wm + mt * 16 + arow) * RS + kk + asel); \
            _Pragma("unroll")                                               \
            for (int np = 0; np < 2; ++np) {                                \
                uint32_t bh4[4];                                            \
                ldsm_x4(bh4, sB + (wn + np * 16 + brow) * RS + kk + bcol);  \
                _Pragma("unroll")                                           \
                for (int half = 0; half < 2; ++half) {                      \
                    const int nt = np * 2 + half;                           \
                    _Pragma("unroll")                                       \
                    for (int mt = 0; mt < 4; ++mt)                          \
                        mma_f16(acc[mt][nt], ah[mt], bh4 + half * 2);       \
                }                                                           \
            }                                                               \
        }                                                                   \
    }

// =================================================================
// Projections: fp16 1-MMA TN GEMM, z-batched over {q,k,v}.
// =================================================================
__global__ void __launch_bounds__(256, 2)
gemm_proj(const h16* __restrict__ A0, const h16* __restrict__ B0, h16* __restrict__ C0,
          const h16* __restrict__ A1, const h16* __restrict__ B1, h16* __restrict__ C1,
          const h16* __restrict__ A2, const h16* __restrict__ B2, h16* __restrict__ C2)
{
    extern __shared__ __align__(16) char smem[];
    const h16* Ax = (blockIdx.z == 0) ? A0 : (blockIdx.z == 1) ? A1 : A2;
    const h16* Bx = (blockIdx.z == 0) ? B0 : (blockIdx.z == 1) ? B1 : B2;
    h16*       Cx = (blockIdx.z == 0) ? C0 : (blockIdx.z == 1) ? C1 : C2;
    const int bm = blockIdx.y * 128, bn = blockIdx.x * 128;

    GEMM_CORE(Ax, Bx)

    const int tr = lane >> 2, tc = lane & 3;
    #pragma unroll
    for (int mt = 0; mt < 4; ++mt) {
        const int row = bm + wm + mt * 16 + tr;
        #pragma unroll
        for (int nt = 0; nt < 4; ++nt) {
            const int col = bn + wn + nt * 8 + tc * 2;
            const float* c = acc[mt][nt];
            *(uint32_t*)&Cx[(long)row * DD + col] =
                pkh(__float2half_rn(c[0]), __float2half_rn(c[1]));
            *(uint32_t*)&Cx[(long)(row + 8) * DD + col] =
                pkh(__float2half_rn(c[2]), __float2half_rn(c[3]));
        }
    }
}

// =================================================================
// Unify GEMM + fused mean/max pooling epilogue.
// =================================================================
__global__ void __launch_bounds__(256, 2)
gemm_uni(const h16* __restrict__ Ain, const h16* __restrict__ Bin,
         const float* __restrict__ bias,
         float* __restrict__ psum, unsigned* __restrict__ pmax)
{
    extern __shared__ __align__(16) char smem[];
    const int bm = blockIdx.y * 128, bn = blockIdx.x * 128;

    GEMM_CORE(Ain, Bin)

    const int tr = lane >> 2, tc = lane & 3;
    const int b = bm >> 10;
    float sum[4][2], mx[4][2];
    #pragma unroll
    for (int nt = 0; nt < 4; ++nt) {
        #pragma unroll
        for (int j = 0; j < 2; ++j) {
            const int col = bn + wn + nt * 8 + tc * 2 + j;
            const float bv = __ldg(bias + col);
            float s_ = 0.f, m_ = -1e30f;
            #pragma unroll
            for (int mt = 0; mt < 4; ++mt) {
                const float v0 = acc[mt][nt][j] + bv;
                const float v1 = acc[mt][nt][j + 2] + bv;
                s_ += v0 + v1;
                m_ = fmaxf(m_, fmaxf(v0, v1));
            }
            sum[nt][j] = s_; mx[nt][j] = m_;
        }
    }
    #pragma unroll
    for (int o = 4; o <= 16; o <<= 1) {
        #pragma unroll
        for (int nt = 0; nt < 4; ++nt)
            #pragma unroll
            for (int j = 0; j < 2; ++j) {
                sum[nt][j] += __shfl_xor_sync(~0u, sum[nt][j], o);
                mx[nt][j] = fmaxf(mx[nt][j], __shfl_xor_sync(~0u, mx[nt][j], o));
            }
    }
    if (tr == 0) {
        #pragma unroll
        for (int nt = 0; nt < 4; ++nt)
            #pragma unroll
            for (int j = 0; j < 2; ++j) {
                const int col = bn + wn + nt * 8 + tc * 2 + j;
                atomicAdd(&psum[b * DD + col], sum[nt][j]);
                atomicMax(&pmax[b * DD + col], fkey(mx[nt][j]));
            }
    }
}

// =================================================================
// Fused flash attention — full fp16 (R15 version).
// =================================================================
__global__ void __launch_bounds__(256, 2)
flash_k(const h16* __restrict__ Q, const h16* __restrict__ K,
        const h16* __restrict__ V, h16* __restrict__ O_)
{
    extern __shared__ __align__(16) char sm[];
    constexpr int QS = 128 * 136;
    constexpr int TS = 64 * 136;
    h16* sQ = (h16*)sm;
    h16* sT = sQ + QS;
    constexpr float SC2 = 0.08838834764831845f;   // 1/sqrt(128)

    const int bh = blockIdx.y, b = bh >> 3, h = bh & 7;
    const int q0 = blockIdx.x * 128;
    const int u = threadIdx.x, wid = u >> 5, lane = u & 31;
    const int tr = lane >> 2, tc = lane & 3;

    const long qg = ((long)b * LL + q0) * DD + h * KHD;
    const long kg = (long)b * LL * DD + h * KHD;

    for (int c = u; c < 2048; c += 256) {
        const int r = c >> 4, s = (c & 15) * 8;
        cpa16(sQ + r * 136 + s, Q + qg + (long)r * DD + s);
    }
    auto stage = [&](int buf, int kv0) {
        h16* pK = sT + buf * 2 * TS;
        h16* pV = pK + TS;
        for (int c = u; c < 1024; c += 256) {
            const int r = c >> 4, s = (c & 15) * 8;
            const long g = kg + (long)(kv0 + r) * DD + s;
            cpa16(pK + r * 136 + s, K + g);
            cpa16(pV + r * 136 + s, V + g);
        }
    };
    stage(0, 0);
    cp_commit();

    float O[16][4];
    #pragma unroll
    for (int i = 0; i < 16; ++i)
        #pragma unroll
        for (int j = 0; j < 4; ++j) O[i][j] = 0.f;
    float m0 = -1e30f, m1 = -1e30f, l0 = 0.f, l1 = 0.f;

    const int brow = ((lane >> 4) & 1) * 8 + (lane & 7);
    const int bcol = ((lane >> 3) & 1) * 8;
    const int vrow = ((lane >> 3) & 1) * 8 + (lane & 7);
    const int vsel = (lane >> 4);

    for (int t = 0; t < 16; ++t) {
        if (t + 1 < 16) stage((t + 1) & 1, (t + 1) * 64);
        cp_commit();
        cp_wait1();
        __syncthreads();

        const h16* cK = sT + (t & 1) * 2 * TS;
        const h16* cV = cK + TS;

        float S[8][4];
        #pragma unroll
        for (int i = 0; i < 8; ++i)
            #pragma unroll
            for (int j = 0; j < 4; ++j) S[i][j] = 0.f;

        #pragma unroll
        for (int kk = 0; kk < 128; kk += 16) {
            uint32_t ah[4];
            const int aoff = (wid * 16 + (lane & 15)) * 136 + kk + (lane >> 4) * 8;
            ldsm_x4(ah, sQ + aoff);
            #pragma unroll
            for (int np = 0; np < 4; ++np) {
                uint32_t bh4[4];
                const int boff = (np * 16 + brow) * 136 + kk + bcol;
                ldsm_x4(bh4, cK + boff);
                mma_f16(S[np * 2],     ah, bh4);
                mma_f16(S[np * 2 + 1], ah, bh4 + 2);
            }
        }

        float rm0 = -1e30f, rm1 = -1e30f;
        #pragma unroll
        for (int nt = 0; nt < 8; ++nt) {
            rm0 = fmaxf(rm0, fmaxf(S[nt][0], S[nt][1]));
            rm1 = fmaxf(rm1, fmaxf(S[nt][2], S[nt][3]));
        }
        rm0 = fmaxf(rm0, __shfl_xor_sync(~0u, rm0, 1));
        rm0 = fmaxf(rm0, __shfl_xor_sync(~0u, rm0, 2));
        rm1 = fmaxf(rm1, __shfl_xor_sync(~0u, rm1, 1));
        rm1 = fmaxf(rm1, __shfl_xor_sync(~0u, rm1, 2));
        const float M0 = fmaxf(m0, rm0), M1 = fmaxf(m1, rm1);
        const float f0 = __expf((m0 - M0) * SC2), f1 = __expf((m1 - M1) * SC2);
        m0 = M0; m1 = M1;
        l0 *= f0; l1 *= f1;
        #pragma unroll
        for (int dt = 0; dt < 16; ++dt) {
            O[dt][0] *= f0; O[dt][1] *= f0;
            O[dt][2] *= f1; O[dt][3] *= f1;
        }

        #pragma unroll
        for (int kc = 0; kc < 4; ++kc) {
            uint32_t pa[4];
            #pragma unroll
            for (int half = 0; half < 2; ++half) {
                const int nt = kc * 2 + half;
                const float p0 = __expf((S[nt][0] - M0) * SC2);
                const float p1 = __expf((S[nt][1] - M0) * SC2);
                const float p2 = __expf((S[nt][2] - M1) * SC2);
                const float p3 = __expf((S[nt][3] - M1) * SC2);
                l0 += p0 + p1; l1 += p2 + p3;
                pa[half ? 2 : 0] = pkh(__float2half_rn(p0), __float2half_rn(p1));
                pa[half ? 3 : 1] = pkh(__float2half_rn(p2), __float2half_rn(p3));
            }
            #pragma unroll
            for (int dt = 0; dt < 16; dt += 2) {
                uint32_t bv[4];
                const int voff = (kc * 16 + vrow) * 136 + (dt + vsel) * 8;
                ldsm_x4t(bv, cV + voff);
                mma_f16(O[dt],     pa, bv);
                mma_f16(O[dt + 1], pa, bv + 2);
            }
        }
        __syncthreads();
    }

    l0 += __shfl_xor_sync(~0u, l0, 1); l0 += __shfl_xor_sync(~0u, l0, 2);
    l1 += __shfl_xor_sync(~0u, l1, 1); l1 += __shfl_xor_sync(~0u, l1, 2);
    const float i0 = 1.f / l0, i1 = 1.f / l1;
    const long og = ((long)b * LL + q0 + wid * 16) * DD + h * KHD;
    #pragma unroll
    for (int dt = 0; dt < 16; ++dt) {
        const int col = dt * 8 + tc * 2;
        *(uint32_t*)&O_[og + (long)tr * DD + col] =
            pkh(__float2half_rn(O[dt][0] * i0), __float2half_rn(O[dt][1] * i0));
        *(uint32_t*)&O_[og + (long)(tr + 8) * DD + col] =
            pkh(__float2half_rn(O[dt][2] * i1), __float2half_rn(O[dt][3] * i1));
    }
}

// ---------------- converts ----------------
__device__ __forceinline__ void conv4_h(const float* in, h16* hi, int i)
{
    const float4 v = ((const float4*)in)[i];
    ((uint32_t*)hi)[i * 2]     = pkh(__float2half_rn(v.x), __float2half_rn(v.y));
    ((uint32_t*)hi)[i * 2 + 1] = pkh(__float2half_rn(v.z), __float2half_rn(v.w));
}

__global__ void conv_x(const float* __restrict__ x1, h16* __restrict__ x1h,
                       const float* __restrict__ x2, h16* __restrict__ x2h,
                       const float* __restrict__ x0, h16* __restrict__ x0h)
{
    const int i = blockIdx.x * 256 + threadIdx.x;
    switch (blockIdx.y) {
        case 0: conv4_h(x1, x1h, i); break;
        case 1: conv4_h(x2, x2h, i); break;
        default: conv4_h(x0, x0h, i); break;
    }
}
// weights + pool-init fused (one launch)
__global__ void conv_w(const float* __restrict__ Wk, h16* __restrict__ wk,
                       const float* __restrict__ Wq, h16* __restrict__ wq,
                       const float* __restrict__ Wv, h16* __restrict__ wv,
                       const float* __restrict__ Wu, h16* __restrict__ wu,
                       float* __restrict__ psum, unsigned* __restrict__ pmax)
{
    const int i = blockIdx.x * 256 + threadIdx.x;
    switch (blockIdx.y) {
        case 0: conv4_h(Wk, wk, i); break;
        case 1: conv4_h(Wq, wq, i); break;
        case 2: conv4_h(Wv, wv, i); break;
        case 3: conv4_h(Wu, wu, i); break;
        default:
            if (i < BB * DD / 4) {
                ((float4*)psum)[i] = make_float4(0.f, 0.f, 0.f, 0.f);
                ((uint4*)pmax)[i]  = make_uint4(0u, 0u, 0u, 0u);
            }
            break;
    }
}

// ---------------- logits ----------------
__global__ void logits_kernel(const float* __restrict__ psum,
                              const unsigned* __restrict__ pmax,
                              const float* __restrict__ Wm,
                              const float* __restrict__ bm,
                              float* __restrict__ out)
{
    const int b = blockIdx.x;
    __shared__ float ps[DD];
    __shared__ float red[4][OUTN];
    for (int i = threadIdx.x; i < DD; i += 256)
        ps[i] = psum[b * DD + i] * (1.f / LL) + fdec(pmax[b * DD + i]);
    __syncthreads();
    const int o = threadIdx.x & 63, part = threadIdx.x >> 6;
    float s = 0.f;
    const float* w = Wm + (long)o * DD + part * 256;
    const float* p = ps + part * 256;
    #pragma unroll 8
    for (int kk = 0; kk < 256; ++kk) s += p[kk] * w[kk];
    red[part][o] = s;
    __syncthreads();
    if (part == 0)
        out[b * OUTN + o] = red[0][o] + red[1][o] + red[2][o] + red[3][o] + bm[o];
}

// =================================================================
extern "C" void kernel_launch(void* const* d_in, const int* in_sizes, int n_in,
                              void* d_out, int out_size)
{
    const float* x0   = (const float*)d_in[0];
    const float* x1   = (const float*)d_in[1];
    const float* x2   = (const float*)d_in[2];
    const float* Wk   = (const float*)d_in[5];
    const float* Wq   = (const float*)d_in[6];
    const float* Wv   = (const float*)d_in[7];
    const float* Wu   = (const float*)d_in[8];
    const float* bu   = (const float*)d_in[9];
    const float* Wmlp = (const float*)d_in[10];
    const float* bmlp = (const float*)d_in[11];
    float* out = (float*)d_out;

    h16 *x0h,*x1h,*x2h,*wk,*wq,*wv,*wu,*qq,*kk,*vv,*att;
    float *psum; unsigned *pmax;
    cudaGetSymbolAddress((void**)&x0h, g_x0h);
    cudaGetSymbolAddress((void**)&x1h, g_x1h);
    cudaGetSymbolAddress((void**)&x2h, g_x2h);
    cudaGetSymbolAddress((void**)&wk,  g_wk);
    cudaGetSymbolAddress((void**)&wq,  g_wq);
    cudaGetSymbolAddress((void**)&wv,  g_wv);
    cudaGetSymbolAddress((void**)&wu,  g_wu);
    cudaGetSymbolAddress((void**)&qq,  g_qq);
    cudaGetSymbolAddress((void**)&kk,  g_kk);
    cudaGetSymbolAddress((void**)&vv,  g_vv);
    cudaGetSymbolAddress((void**)&att, g_att);
    cudaGetSymbolAddress((void**)&psum, g_psum);
    cudaGetSymbolAddress((void**)&pmax, g_pmax);

    const int M = BB * LL;

    constexpr int SM_PRJ = 4 * 2 * 128 * 40 * 2;               // 81920
    constexpr int SM_FL  = (128 * 136 + 2 * 2 * 64 * 136) * 2; // 104448
    cudaFuncSetAttribute(gemm_proj, cudaFuncAttributeMaxDynamicSharedMemorySize, SM_PRJ);
    cudaFuncSetAttribute(gemm_uni,  cudaFuncAttributeMaxDynamicSharedMemorySize, SM_PRJ);
    cudaFuncSetAttribute(flash_k,   cudaFuncAttributeMaxDynamicSharedMemorySize, SM_FL);

    // --- converts (+ fused pool init) ---
    {
        dim3 gx(BB * LL * DD / 4 / 256, 3);
        conv_x<<<gx, 256>>>(x1, x1h, x2, x2h, x0, x0h);
        dim3 gw(DD * DD / 4 / 256, 5);
        conv_w<<<gw, 256>>>(Wk, wk, Wq, wq, Wv, wv, Wu, wu, psum, pmax);
    }

    dim3 blk(256);

    // --- q, k, v projections (one z=3 launch) ---
    {
        dim3 g3(DD / 128, M / 128, 3);
        gemm_proj<<<g3, blk, SM_PRJ>>>(x2h, wk, qq,
                                       x1h, wq, kk,
                                       x0h, wv, vv);
    }

    // --- fused attention ---
    {
        dim3 grid(LL / 128, BB * HH);
        flash_k<<<grid, blk, SM_FL>>>(qq, kk, vv, att);
    }

    // --- unify + fused pooling ---
    {
        dim3 g1(DD / 128, M / 128);
        gemm_uni<<<g1, blk, SM_PRJ>>>(att, wu, bu, psum, pmax);
    }

    // --- logits ---
    logits_kernel<<<BB, 256>>>(psum, pmax, Wmlp, bmlp, out);
}